// round 16
// baseline (speedup 1.0000x reference)
#include <cuda_runtime.h>
#include <cuda_fp16.h>
#include <math.h>
#include <stdint.h>

// ---------------------------------------------------------------------------
// Problem constants: B=2, S=2048, HID=2048, NH=16, NKV=4, HD=256
// ---------------------------------------------------------------------------
#define ROWS      4096
#define HID       2048
#define NH        16
#define NKV       4
#define HD        256
#define SQ        2048
#define QCOLS     (NH * HD)    // 4096
#define KCOLS     (NKV * HD)   // 1024
#define NQKV      (QCOLS + 2 * KCOLS)   // 6144

// Scratch (static device globals -- no allocation anywhere)
__device__ __half g_Qh[(size_t)ROWS * QCOLS];                 // rope'd, scaled, PERMUTED dims
__device__ __half g_Kh[(size_t)ROWS * KCOLS];                 // rope'd, PERMUTED dims
__device__ __half g_Vh[(size_t)ROWS * KCOLS];                 // V fp16 linear
__device__ __half g_Vt[(size_t)(2 * NKV) * HD * SQ];          // [b*kvh][dim][key]
__device__ __half g_Ah[(size_t)ROWS * QCOLS];                 // attention out fp16
__device__ __half g_Xh[(size_t)ROWS * HID];                   // hidden fp16
__device__ __half g_Wqkv[(size_t)NQKV * HID];                 // [N][K]: Q(perm)|K(perm)|V
__device__ __half g_WoT[(size_t)HID * QCOLS];
__device__ float  g_invfreq[128];

// ---------------------------------------------------------------------------
// Helpers
// ---------------------------------------------------------------------------
__device__ __forceinline__ uint32_t pack_half2(float a, float b) {
    uint32_t r;
    asm("cvt.rn.f16x2.f32 %0, %2, %1;" : "=r"(r) : "f"(a), "f"(b));
    return r;
}

__device__ __forceinline__ void cpa16(uint32_t saddr, const void* gaddr) {
    asm volatile("cp.async.cg.shared.global [%0], [%1], 16;"
                 :: "r"(saddr), "l"(gaddr));
}
#define CP_COMMIT() asm volatile("cp.async.commit_group;")
#define CP_WAIT1()  asm volatile("cp.async.wait_group 1;")

__device__ __forceinline__ void ldsm_x4(uint32_t* r, uint32_t saddr) {
    asm volatile("ldmatrix.sync.aligned.m8n8.x4.shared.b16 {%0,%1,%2,%3}, [%4];"
                 : "=r"(r[0]), "=r"(r[1]), "=r"(r[2]), "=r"(r[3])
                 : "r"(saddr));
}

#define MMA_FP16(d, a, b)                                                      \
    asm volatile(                                                              \
        "mma.sync.aligned.m16n8k16.row.col.f32.f16.f16.f32 "                   \
        "{%0,%1,%2,%3},{%4,%5,%6,%7},{%8,%9},{%0,%1,%2,%3};"                   \
        : "+f"((d)[0]), "+f"((d)[1]), "+f"((d)[2]), "+f"((d)[3])               \
        : "r"((a)[0]), "r"((a)[1]), "r"((a)[2]), "r"((a)[3]),                  \
          "r"((b)[0]), "r"((b)[1]))

// ---------------------------------------------------------------------------
// GEMM mainloop: CTA tile 128x256, BK=64, 8 warps (2 in M x 4 in N),
// warp tile 64x64. 3-slot cp.async ring, 1 sync/iter, stride-72 smem rows
// (9 x 16B, odd -> conflict-free ldmatrix). A rows [0,128), B rows [0,256)
// contiguous per stage.
// ---------------------------------------------------------------------------
#define GLDK   72
#define STG_H  (384 * GLDK)            // halves per stage (A 128 rows + B 256)
#define BOFF_H (128 * GLDK)            // B offset within stage (halves)
#define GEMM_SMEM_BYTES (3 * STG_H * 2)  // 165888

__device__ __forceinline__ void g_load_stage(
    uint32_t sbase, int slot, const __half* Ab, const __half* Bb,
    int K, int tid, int ko)
{
    const uint32_t stg = sbase + (uint32_t)(slot * STG_H) * 2;
#pragma unroll
    for (int i = 0; i < 12; i++) {
        const int c = tid + i * 256;          // 0..3071
        const int row = c >> 3, col8 = c & 7; // 384 rows x 8 chunks
        const uint32_t so = (uint32_t)(row * GLDK + col8 * 8) * 2;
        const __half* gsrc = (row < 128)
            ? (Ab + (size_t)row * K + ko + col8 * 8)
            : (Bb + (size_t)(row - 128) * K + ko + col8 * 8);
        cpa16(stg + so, gsrc);
    }
}

#define GEMM_MAINLOOP(A_, Bt_, K_)                                             \
    const uint32_t sbase = (uint32_t)__cvta_generic_to_shared(sh);             \
    const uint32_t a_lm = (uint32_t)((wm + (lane & 15)) * GLDK +               \
                                     (lane >> 4) * 8) * 2;                     \
    const uint32_t b_lm = (uint32_t)((wn + (lane >> 4) * 8 + (lane & 7)) *     \
                                     GLDK + ((lane >> 3) & 1) * 8) * 2;        \
    float acc[4][8][4];                                                        \
    _Pragma("unroll")                                                          \
    for (int mi = 0; mi < 4; mi++)                                             \
        _Pragma("unroll")                                                      \
        for (int ni = 0; ni < 8; ni++)                                         \
            _Pragma("unroll")                                                  \
            for (int e = 0; e < 4; e++) acc[mi][ni][e] = 0.f;                  \
    const __half* Abase = (A_)  + (size_t)row0 * (K_);                         \
    const __half* Bbase = (Bt_) + (size_t)col0 * (K_);                         \
    const int nk = (K_) >> 6;                                                  \
    g_load_stage(sbase, 0, Abase, Bbase, (K_), tid, 0);  CP_COMMIT();          \
    g_load_stage(sbase, 1, Abase, Bbase, (K_), tid, 64); CP_COMMIT();          \
    for (int kt = 0; kt < nk; kt++) {                                          \
        CP_WAIT1();                                                            \
        __syncthreads();                                                       \
        if (kt + 2 < nk)                                                       \
            g_load_stage(sbase, (kt + 2) % 3, Abase, Bbase, (K_), tid,         \
                         (kt + 2) * 64);                                       \
        CP_COMMIT();                                                           \
        const uint32_t sAl = sbase + (uint32_t)((kt % 3) * STG_H) * 2;         \
        const uint32_t sBl = sAl + (uint32_t)BOFF_H * 2;                       \
        _Pragma("unroll")                                                      \
        for (int kc = 0; kc < 4; kc++) {                                       \
            uint32_t af[4][4], bf[8][2];                                       \
            _Pragma("unroll")                                                  \
            for (int mi = 0; mi < 4; mi++)                                     \
                ldsm_x4(af[mi], sAl + a_lm +                                   \
                        (uint32_t)(mi * 16 * GLDK + kc * 16) * 2);             \
            _Pragma("unroll")                                                  \
            for (int p = 0; p < 4; p++) {                                      \
                uint32_t bq[4];                                                \
                ldsm_x4(bq, sBl + b_lm +                                       \
                        (uint32_t)(p * 16 * GLDK + kc * 16) * 2);              \
                bf[2 * p][0]     = bq[0];                                      \
                bf[2 * p][1]     = bq[1];                                      \
                bf[2 * p + 1][0] = bq[2];                                      \
                bf[2 * p + 1][1] = bq[3];                                      \
            }                                                                  \
            _Pragma("unroll")                                                  \
            for (int mi = 0; mi < 4; mi++)                                     \
                _Pragma("unroll")                                              \
                for (int ni = 0; ni < 8; ni++)                                 \
                    MMA_FP16(acc[mi][ni], af[mi], bf[ni]);                     \
        }                                                                      \
    }

// ---------------------------------------------------------------------------
// Fused QKV projection: C = Xh @ Wqkv^T, N = 6144, CTA cols 256.
// Region boundaries (4096, 5120, 6144) are 256-aligned -> per-CTA uniform.
// ---------------------------------------------------------------------------
__global__ __launch_bounds__(256, 1) void gemm_qkv(
    const __half* __restrict__ A, const __half* __restrict__ Bt,
    const int* __restrict__ pos, __half* __restrict__ Qh,
    __half* __restrict__ Kh, __half* __restrict__ Vh)
{
    extern __shared__ __half sh[];
    const int tid  = threadIdx.x;
    const int wid  = tid >> 5;
    const int lane = tid & 31;
    const int g    = lane >> 2;
    const int tg   = lane & 3;
    const int wm   = (wid & 1) * 64;
    const int wn   = (wid >> 1) * 64;
    const int row0 = blockIdx.y * 128;
    const int col0 = blockIdx.x * 256;

    GEMM_MAINLOOP(A, Bt, HID)

    if (col0 >= QCOLS + KCOLS) {
        // V region: plain fp16 store
#pragma unroll
        for (int mi = 0; mi < 4; mi++) {
#pragma unroll
            for (int ni = 0; ni < 8; ni++) {
                const int r  = row0 + wm + mi * 16 + g;
                const int cc = col0 - QCOLS - KCOLS + wn + ni * 8 + tg * 2;
                *(uint32_t*)&Vh[(size_t)r * KCOLS + cc] =
                    pack_half2(acc[mi][ni][0], acc[mi][ni][1]);
                *(uint32_t*)&Vh[(size_t)(r + 8) * KCOLS + cc] =
                    pack_half2(acc[mi][ni][2], acc[mi][ni][3]);
            }
        }
    } else {
        const bool isQ = (col0 < QCOLS);
        const float scale = isQ ? 0.0625f : 1.0f;
        __half* dst = isQ ? Qh : Kh;
        const int cols = isQ ? QCOLS : KCOLS;
        const int cbase = isQ ? col0 : col0 - QCOLS;
#pragma unroll
        for (int mi = 0; mi < 4; mi++) {
            const int r = row0 + wm + mi * 16 + g;
            const float p0 = (float)pos[r];
            const float p1 = (float)pos[r + 8];
#pragma unroll
            for (int ni = 0; ni < 8; ni++) {
                const int cc = cbase + wn + ni * 8 + tg * 2;
                const int i  = (cc & 255) >> 1;     // rope index within head
                const float invf = g_invfreq[i];
                float s0, c0, s1, c1;
                sincosf(p0 * invf, &s0, &c0);
                sincosf(p1 * invf, &s1, &c1);
                const float x1a = acc[mi][ni][0], x2a = acc[mi][ni][1];
                const float x1b = acc[mi][ni][2], x2b = acc[mi][ni][3];
                *(uint32_t*)&dst[(size_t)r * cols + cc] =
                    pack_half2((x1a * c0 - x2a * s0) * scale,
                               (x2a * c0 + x1a * s0) * scale);
                *(uint32_t*)&dst[(size_t)(r + 8) * cols + cc] =
                    pack_half2((x1b * c1 - x2b * s1) * scale,
                               (x2b * c1 + x1b * s1) * scale);
            }
        }
    }
}

// ---------------------------------------------------------------------------
// Output projection GEMM: fp32 out (final result)
// ---------------------------------------------------------------------------
__global__ __launch_bounds__(256, 1) void gemm_f16(
    const __half* __restrict__ A, const __half* __restrict__ Bt,
    float* __restrict__ C, int M, int N, int K)
{
    extern __shared__ __half sh[];
    const int tid  = threadIdx.x;
    const int wid  = tid >> 5;
    const int lane = tid & 31;
    const int g    = lane >> 2;
    const int tg   = lane & 3;
    const int wm   = (wid & 1) * 64;
    const int wn   = (wid >> 1) * 64;
    const int row0 = blockIdx.y * 128;
    const int col0 = blockIdx.x * 256;

    GEMM_MAINLOOP(A, Bt, K)

#pragma unroll
    for (int mi = 0; mi < 4; mi++) {
#pragma unroll
        for (int ni = 0; ni < 8; ni++) {
            const int r  = row0 + wm + mi * 16 + g;
            const int cc = col0 + wn + ni * 8 + tg * 2;
            *(float2*)&C[(size_t)r * N + cc] =
                make_float2(acc[mi][ni][0], acc[mi][ni][1]);
            *(float2*)&C[(size_t)(r + 8) * N + cc] =
                make_float2(acc[mi][ni][2], acc[mi][ni][3]);
        }
    }
}

// ---------------------------------------------------------------------------
// fp32 -> fp16 (vectorized)
// ---------------------------------------------------------------------------
__global__ void f2h(const float* __restrict__ in, __half* __restrict__ out, int n)
{
    const int i = blockIdx.x * blockDim.x + threadIdx.x;
    if (i * 4 >= n) return;
    const float4 v = ((const float4*)in)[i];
    uint2 h;
    h.x = pack_half2(v.x, v.y);
    h.y = pack_half2(v.z, v.w);
    ((uint2*)out)[i] = h;
}

// ---------------------------------------------------------------------------
// Weight transpose+convert: W[K][N] fp32 -> Wt[N][K] fp16.
// perm != 0: rope-pair-adjacent permutation of the output row within a head.
// ---------------------------------------------------------------------------
__global__ void wtrans(const float* __restrict__ W, __half* __restrict__ Wt,
                       int K, int N, int perm)
{
    __shared__ float tile[32][33];
    const int x = threadIdx.x, y = threadIdx.y;
    const int n0 = blockIdx.x * 32, k0 = blockIdx.y * 32;
#pragma unroll
    for (int j = 0; j < 4; j++)
        tile[y + j * 8][x] = W[(size_t)(k0 + y + j * 8) * N + n0 + x];
    __syncthreads();
#pragma unroll
    for (int j = 0; j < 4; j++) {
        int n = n0 + y + j * 8;
        if (perm) {
            const int d = n & 255;
            n = (n & ~255) | ((d < 128) ? (2 * d) : (2 * (d - 128) + 1));
        }
        Wt[(size_t)n * K + k0 + x] = __float2half_rn(tile[x][y + j * 8]);
    }
}

// ---------------------------------------------------------------------------
// inv_freq table (fp64 exp once)
// ---------------------------------------------------------------------------
__global__ void init_invfreq()
{
    const int i = threadIdx.x;
    g_invfreq[i] = (float)exp(-((double)(2 * i) / 256.0) * log(10000.0));
}

// ---------------------------------------------------------------------------
// V transpose (fp16 in): [b*S][kvh*256+d] -> [b*kvh][d][s]
// ---------------------------------------------------------------------------
__global__ void vtrans(const __half* __restrict__ V, __half* __restrict__ Vt)
{
    __shared__ float tile[32][33];
    const int s0 = blockIdx.x * 32, d0 = blockIdx.y * 32, bk = blockIdx.z;
    const int b = bk >> 2, kvh = bk & 3;
    const int x = threadIdx.x, y = threadIdx.y;
#pragma unroll
    for (int j = 0; j < 4; j++)
        tile[y + j * 8][x] = __half2float(
            V[(size_t)(b * SQ + s0 + y + j * 8) * KCOLS + kvh * HD + d0 + x]);
    __syncthreads();
#pragma unroll
    for (int j = 0; j < 4; j++)
        Vt[((size_t)bk * HD + d0 + y + j * 8) * SQ + s0 + x] =
            __float2half_rn(tile[x][y + j * 8]);
}

// ---------------------------------------------------------------------------
// fp16 tensor-core causal flash attention (proven R11-R14). fp16 out.
// ---------------------------------------------------------------------------
#define QK_LDH 264
#define VT_LDH 72
#define FL_SMEM_BYTES ((2 * 64 * QK_LDH + 256 * VT_LDH) * 2)

__global__ __launch_bounds__(128) void flash16(
    const __half* __restrict__ Q, const __half* __restrict__ K,
    const __half* __restrict__ Vt, __half* __restrict__ O)
{
    extern __shared__ __half sh[];
    __half* Qs = sh;
    __half* Ks = Qs + 64 * QK_LDH;
    __half* Vs = Ks + 64 * QK_LDH;

    const int tid  = threadIdx.x;
    const int lane = tid & 31;
    const int w    = tid >> 5;
    const int g    = lane >> 2;
    const int tg   = lane & 3;
    const int qt   = 31 - blockIdx.x;
    const int h    = blockIdx.y;
    const int b    = blockIdx.z;
    const int kvh  = h >> 2;
    const int qrow0 = qt * 64;
    const int wr   = w * 16;

    const uint32_t q_lm = (uint32_t)((wr + (lane & 15)) * QK_LDH +
                                     (lane >> 4) * 8) * 2;
    const uint32_t k_lm = (uint32_t)(((lane >> 4) * 8 + (lane & 7)) * QK_LDH +
                                     ((lane >> 3) & 1) * 8) * 2;
    const uint32_t v_lm = (uint32_t)(((lane >> 4) * 8 + (lane & 7)) * VT_LDH +
                                     ((lane >> 3) & 1) * 8) * 2;
    const uint32_t sQ = (uint32_t)__cvta_generic_to_shared(Qs) + q_lm;
    const uint32_t sK = (uint32_t)__cvta_generic_to_shared(Ks) + k_lm;
    const uint32_t sV = (uint32_t)__cvta_generic_to_shared(Vs) + v_lm;

    {
        const __half* Qg = Q + (size_t)(b * SQ + qrow0) * QCOLS + h * HD;
#pragma unroll
        for (int it = 0; it < 16; it++) {
            const int idx = tid + it * 128;
            const int r = idx >> 5, c8 = idx & 31;
            *(uint4*)&Qs[r * QK_LDH + c8 * 8] =
                *(const uint4*)&Qg[(size_t)r * QCOLS + c8 * 8];
        }
    }

    float o[32][4];
#pragma unroll
    for (int jd = 0; jd < 32; jd++)
#pragma unroll
        for (int e = 0; e < 4; e++) o[jd][e] = 0.f;
    float m0 = -1e30f, m1 = -1e30f, l0 = 0.f, l1 = 0.f;
    __syncthreads();

    for (int kt = 0; kt <= qt; kt++) {
        {
            const __half* Kg = K + (size_t)(b * SQ + kt * 64) * KCOLS + kvh * HD;
            const __half* Vg = Vt + ((size_t)(b * NKV + kvh) * HD) * SQ + kt * 64;
#pragma unroll
            for (int it = 0; it < 16; it++) {
                const int idx = tid + it * 128;
                const int r = idx >> 5, c8 = idx & 31;
                *(uint4*)&Ks[r * QK_LDH + c8 * 8] =
                    *(const uint4*)&Kg[(size_t)r * KCOLS + c8 * 8];
                const int d = idx >> 3, k8 = idx & 7;
                *(uint4*)&Vs[d * VT_LDH + k8 * 8] =
                    *(const uint4*)&Vg[(size_t)d * SQ + k8 * 8];
            }
        }
        __syncthreads();

        float s[8][4];
#pragma unroll
        for (int j = 0; j < 8; j++)
#pragma unroll
            for (int e = 0; e < 4; e++) s[j][e] = 0.f;

#pragma unroll
        for (int kc = 0; kc < 16; kc++) {
            uint32_t a[4];
            ldsm_x4(a, sQ + (uint32_t)(kc * 16) * 2);
#pragma unroll
            for (int p = 0; p < 4; p++) {
                uint32_t kq[4];
                ldsm_x4(kq, sK + (uint32_t)(p * 16 * QK_LDH + kc * 16) * 2);
                MMA_FP16(s[2 * p],     a, (kq + 0));
                MMA_FP16(s[2 * p + 1], a, (kq + 2));
            }
        }

        if (kt == qt) {
            const int r0 = wr + g, r1 = wr + g + 8;
#pragma unroll
            for (int j = 0; j < 8; j++) {
                const int c0 = j * 8 + 2 * tg, c1 = c0 + 1;
                if (c0 > r0) s[j][0] = -1e30f;
                if (c1 > r0) s[j][1] = -1e30f;
                if (c0 > r1) s[j][2] = -1e30f;
                if (c1 > r1) s[j][3] = -1e30f;
            }
        }

        float tm0 = -1e30f, tm1 = -1e30f;
#pragma unroll
        for (int j = 0; j < 8; j++) {
            tm0 = fmaxf(tm0, fmaxf(s[j][0], s[j][1]));
            tm1 = fmaxf(tm1, fmaxf(s[j][2], s[j][3]));
        }
        tm0 = fmaxf(tm0, __shfl_xor_sync(0xffffffffu, tm0, 1));
        tm0 = fmaxf(tm0, __shfl_xor_sync(0xffffffffu, tm0, 2));
        tm1 = fmaxf(tm1, __shfl_xor_sync(0xffffffffu, tm1, 1));
        tm1 = fmaxf(tm1, __shfl_xor_sync(0xffffffffu, tm1, 2));

        const float mn0 = fmaxf(m0, tm0), mn1 = fmaxf(m1, tm1);
        const float cf0 = __expf(m0 - mn0), cf1 = __expf(m1 - mn1);
        m0 = mn0; m1 = mn1;

        uint32_t pf[8][2];
        float ls0 = 0.f, ls1 = 0.f;
#pragma unroll
        for (int j = 0; j < 8; j++) {
            const float p00 = __expf(s[j][0] - m0);
            const float p01 = __expf(s[j][1] - m0);
            const float p10 = __expf(s[j][2] - m1);
            const float p11 = __expf(s[j][3] - m1);
            ls0 += p00 + p01;
            ls1 += p10 + p11;
            pf[j][0] = pack_half2(p00, p01);
            pf[j][1] = pack_half2(p10, p11);
        }
        ls0 += __shfl_xor_sync(0xffffffffu, ls0, 1);
        ls0 += __shfl_xor_sync(0xffffffffu, ls0, 2);
        ls1 += __shfl_xor_sync(0xffffffffu, ls1, 1);
        ls1 += __shfl_xor_sync(0xffffffffu, ls1, 2);
        l0 = l0 * cf0 + ls0;
        l1 = l1 * cf1 + ls1;

#pragma unroll
        for (int jd = 0; jd < 32; jd++) {
            o[jd][0] *= cf0; o[jd][1] *= cf0;
            o[jd][2] *= cf1; o[jd][3] *= cf1;
        }
#pragma unroll
        for (int kc = 0; kc < 4; kc++) {
            uint32_t a[4] = { pf[2 * kc][0], pf[2 * kc][1],
                              pf[2 * kc + 1][0], pf[2 * kc + 1][1] };
#pragma unroll
            for (int p = 0; p < 16; p++) {
                uint32_t vq[4];
                ldsm_x4(vq, sV + (uint32_t)(p * 16 * VT_LDH + kc * 16) * 2);
                MMA_FP16(o[2 * p],     a, (vq + 0));
                MMA_FP16(o[2 * p + 1], a, (vq + 2));
            }
        }
        __syncthreads();
    }

    const float inv0 = 1.0f / l0, inv1 = 1.0f / l1;
    const size_t r0 = (size_t)(b * SQ + qrow0 + wr + g) * QCOLS + h * HD;
    const size_t r1 = (size_t)(b * SQ + qrow0 + wr + g + 8) * QCOLS + h * HD;
#pragma unroll
    for (int jd = 0; jd < 32; jd++) {
        const int cc = jd * 8 + 2 * tg;
        *(uint32_t*)&O[r0 + cc] = pack_half2(o[jd][0] * inv0, o[jd][1] * inv0);
        *(uint32_t*)&O[r1 + cc] = pack_half2(o[jd][2] * inv1, o[jd][3] * inv1);
    }
}

// ---------------------------------------------------------------------------
// Launch. inputs: hidden_states, attention_mask, position_ids, Wq, Wk, Wv, Wo
// gemm_qkv is launch index 5 (0-based) so ncu -s 5 -c 1 profiles it.
// ---------------------------------------------------------------------------
extern "C" void kernel_launch(void* const* d_in, const int* in_sizes, int n_in,
                              void* d_out, int out_size)
{
    const float* X   = (const float*)d_in[0];
    const int*   pos = (const int*)d_in[2];
    const float* Wq  = (const float*)d_in[3];
    const float* Wk  = (const float*)d_in[4];
    const float* Wv  = (const float*)d_in[5];
    const float* Wo  = (const float*)d_in[6];
    float* out = (float*)d_out;

    __half *Qh, *Kh, *Vh, *Vth, *Ah, *Xh, *Wqkv, *WoT;
    cudaGetSymbolAddress((void**)&Qh,   g_Qh);
    cudaGetSymbolAddress((void**)&Kh,   g_Kh);
    cudaGetSymbolAddress((void**)&Vh,   g_Vh);
    cudaGetSymbolAddress((void**)&Vth,  g_Vt);
    cudaGetSymbolAddress((void**)&Ah,   g_Ah);
    cudaGetSymbolAddress((void**)&Xh,   g_Xh);
    cudaGetSymbolAddress((void**)&Wqkv, g_Wqkv);
    cudaGetSymbolAddress((void**)&WoT,  g_WoT);

    cudaFuncSetAttribute(gemm_qkv, cudaFuncAttributeMaxDynamicSharedMemorySize,
                         GEMM_SMEM_BYTES);
    cudaFuncSetAttribute(gemm_f16, cudaFuncAttributeMaxDynamicSharedMemorySize,
                         GEMM_SMEM_BYTES);
    cudaFuncSetAttribute(flash16, cudaFuncAttributeMaxDynamicSharedMemorySize,
                         FL_SMEM_BYTES);

    init_invfreq<<<1, 128>>>();                                      // 0
    f2h<<<(ROWS * HID / 4 + 255) / 256, 256>>>(X, Xh, ROWS * HID);   // 1

    // Build fused weight matrix [N=6144][K=2048]: Q (perm) | K (perm) | V
    wtrans<<<dim3(QCOLS / 32, HID / 32), dim3(32, 8)>>>(             // 2
        Wq, Wqkv, HID, QCOLS, 1);
    wtrans<<<dim3(KCOLS / 32, HID / 32), dim3(32, 8)>>>(             // 3
        Wk, Wqkv + (size_t)QCOLS * HID, HID, KCOLS, 1);
    wtrans<<<dim3(KCOLS / 32, HID / 32), dim3(32, 8)>>>(             // 4
        Wv, Wqkv + (size_t)(QCOLS + KCOLS) * HID, HID, KCOLS, 0);

    // 5: Fused QKV projection + RoPE + fp16 (ncu profiles this one)
    gemm_qkv<<<dim3(NQKV / 256, ROWS / 128), 256, GEMM_SMEM_BYTES>>>(
        Xh, Wqkv, pos, Qh, Kh, Vh);

    wtrans<<<dim3(HID / 32, QCOLS / 32), dim3(32, 8)>>>(             // 6
        Wo, WoT, QCOLS, HID, 0);

    // V -> transposed fp16 [b*kvh][d][s]
    vtrans<<<dim3(SQ / 32, HD / 32, 2 * NKV), dim3(32, 8)>>>(Vh, Vth);

    // fp16 tensor-core causal flash attention -> fp16 output
    flash16<<<dim3(SQ / 64, NH, 2), 128, FL_SMEM_BYTES>>>(Qh, Kh, Vth, Ah);

    // Output projection -> fp32 final output
    gemm_f16<<<dim3(HID / 256, ROWS / 128), 256, GEMM_SMEM_BYTES>>>(
        Ah, WoT, out, ROWS, HID, QCOLS);
}